// round 13
// baseline (speedup 1.0000x reference)
#include <cuda_runtime.h>
#include <cuda_bf16.h>
#include <cuda_fp16.h>
#include <math.h>

#define N_NODES 50000
#define BATCH   512
#define F0      78
#define NH1     10
#define D1      780
#define C2      128
#define EMBD    128
#define SEQ     1000
#define VOCAB   26
#define KW      8
#define NF      32
#define LOUT    121
#define E_TOT   250000

#define H1W     800
#define ALS1    780
#define ALD1    790
#define H1BW    416
#define K2_X    39
#define K2_D1   390
#define K2_CV   104
#define K2_XT   1936
#define K2_F1   128
#define K2_F2   512

// ---------------- scratch ----------------
__device__ unsigned g_h1b  [N_NODES * H1BW];
__device__ unsigned g_xF   [N_NODES * K2_X];
__device__ unsigned g_w1F  [H1W * K2_X];
__device__ unsigned g_h1eF [N_NODES * K2_D1];
__device__ unsigned g_w2F  [C2 * K2_D1];
__device__ float    g_ws   [D1], g_wd[D1];
__device__ float    g_als2 [N_NODES], g_ald2[N_NODES];
__device__ float    g_h2   [N_NODES * C2];
__device__ float    g_o2   [N_NODES * C2];
__device__ unsigned g_AH   [BATCH * NF * K2_CV], g_AL [BATCH * NF * K2_CV];
__device__ unsigned g_EkH  [LOUT * K2_CV],     g_EkL  [LOUT * K2_CV];
__device__ float    g_conv [BATCH * NF * LOUT];
__device__ unsigned g_cvH  [BATCH * K2_XT],    g_cvL  [BATCH * K2_XT];
__device__ unsigned g_fxtH [C2 * K2_XT],       g_fxtL [C2 * K2_XT];
__device__ float    g_xt   [BATCH * C2];
__device__ unsigned g_xcH  [BATCH * K2_F1],    g_xcL  [BATCH * K2_F1];
__device__ unsigned g_f1wH [1024 * K2_F1],     g_f1wL [1024 * K2_F1];
__device__ unsigned g_f1H  [BATCH * K2_F2],    g_f1L  [BATCH * K2_F2];
__device__ unsigned g_f2wH [256 * K2_F2],      g_f2wL [256 * K2_F2];
__device__ float    g_f2   [BATCH * 256];
__device__ int g_deg[N_NODES], g_off[N_NODES + 1], g_cur[N_NODES];
__device__ int g_srcs[E_TOT], g_starts[BATCH + 1];

// ---------------- helpers ----------------
__device__ __forceinline__ void bf16_split(float v, unsigned short& h, unsigned short& l) {
    __nv_bfloat16 hb = __float2bfloat16(v);
    float r = v - __bfloat162float(hb);
    __nv_bfloat16 lb = __float2bfloat16(r);
    h = __bfloat16_as_ushort(hb);
    l = __bfloat16_as_ushort(lb);
}
__device__ __forceinline__ void split2pack(float v0, float v1, unsigned& H, unsigned& L) {
    unsigned short h0, l0, h1, l1;
    bf16_split(v0, h0, l0);
    bf16_split(v1, h1, l1);
    H = ((unsigned)h1 << 16) | h0;
    L = ((unsigned)l1 << 16) | l0;
}
__device__ __forceinline__ unsigned packHalf2(float v0, float v1) {
    __half2 h = __floats2half2_rn(v0, v1);
    return *reinterpret_cast<unsigned*>(&h);
}
__device__ __forceinline__ void mma_bf16(float* c, const unsigned* a, const unsigned* b) {
    asm volatile(
        "mma.sync.aligned.m16n8k16.row.col.f32.bf16.bf16.f32 "
        "{%0,%1,%2,%3}, {%4,%5,%6,%7}, {%8,%9}, {%0,%1,%2,%3};\n"
        : "+f"(c[0]), "+f"(c[1]), "+f"(c[2]), "+f"(c[3])
        : "r"(a[0]), "r"(a[1]), "r"(a[2]), "r"(a[3]), "r"(b[0]), "r"(b[1]));
}
__device__ __forceinline__ void mma_f16(float* c, const unsigned* a, const unsigned* b) {
    asm volatile(
        "mma.sync.aligned.m16n8k16.row.col.f32.f16.f16.f32 "
        "{%0,%1,%2,%3}, {%4,%5,%6,%7}, {%8,%9}, {%0,%1,%2,%3};\n"
        : "+f"(c[0]), "+f"(c[1]), "+f"(c[2]), "+f"(c[3])
        : "r"(a[0]), "r"(a[1]), "r"(a[2]), "r"(a[3]), "r"(b[0]), "r"(b[1]));
}
__device__ __forceinline__ void ldsm_x4(unsigned& r0, unsigned& r1, unsigned& r2, unsigned& r3,
                                        unsigned addr) {
    asm volatile("ldmatrix.sync.aligned.m8n8.x4.shared.b16 {%0,%1,%2,%3}, [%4];"
        : "=r"(r0), "=r"(r1), "=r"(r2), "=r"(r3) : "r"(addr));
}

// ---------------- CSR build ----------------
__global__ void deg_init_k(int* deg) {
    int i = blockIdx.x * blockDim.x + threadIdx.x;
    if (i < N_NODES) deg[i] = 1;
}
__global__ void hist_k(const int* __restrict__ ei, int* deg, int E) {
    int e = blockIdx.x * blockDim.x + threadIdx.x;
    if (e < E) atomicAdd(&deg[ei[E + e]], 1);
}
__global__ void scan_k(const int* __restrict__ deg, int* off, int n) {
    __shared__ int wsum[32];
    __shared__ int carry_s;
    int tid = threadIdx.x, lane = tid & 31, w = tid >> 5;
    if (tid == 0) { carry_s = 0; off[0] = 0; }
    __syncthreads();
    for (int base = 0; base < n; base += 1024) {
        int x = (base + tid < n) ? deg[base + tid] : 0;
#pragma unroll
        for (int o = 1; o < 32; o <<= 1) {
            int y = __shfl_up_sync(0xffffffffu, x, o);
            if (lane >= o) x += y;
        }
        if (lane == 31) wsum[w] = x;
        __syncthreads();
        if (w == 0) {
            int s = wsum[lane];
#pragma unroll
            for (int o = 1; o < 32; o <<= 1) {
                int y = __shfl_up_sync(0xffffffffu, s, o);
                if (lane >= o) s += y;
            }
            wsum[lane] = s;
        }
        __syncthreads();
        int woff = (w == 0) ? 0 : wsum[w - 1];
        if (base + tid < n) off[base + tid + 1] = carry_s + woff + x;
        __syncthreads();
        if (tid == 0) carry_s += wsum[31];
        __syncthreads();
    }
}
__global__ void selfloop_k(const int* __restrict__ off, int* cur, int* srcs) {
    int i = blockIdx.x * blockDim.x + threadIdx.x;
    if (i < N_NODES) { int b = off[i]; srcs[b] = i; cur[i] = b + 1; }
}
__global__ void fill_k(const int* __restrict__ ei, int* cur, int* srcs, int E) {
    int e = blockIdx.x * blockDim.x + threadIdx.x;
    if (e < E) {
        int d = ei[E + e];
        int p = atomicAdd(&cur[d], 1);
        srcs[p] = ei[e];
    }
}

// ---------------- mega prep ----------------
#define PB_X   7618
#define PB_W1  (PB_X + 122)
#define PB_W2  (PB_W1 + 195)
#define PB_WS  (PB_W2 + 7)
#define PB_FXT (PB_WS + 968)
#define PB_F1  (PB_FXT + 512)
#define PB_F2  (PB_F1 + 512)
#define PB_EK  (PB_F2 + 50)
__global__ void prep_k(const float* __restrict__ x,
                       const float* __restrict__ W1, const float* __restrict__ as1, const float* __restrict__ ad1,
                       const float* __restrict__ W2, const float* __restrict__ as2, const float* __restrict__ ad2,
                       const float* __restrict__ fxtw,
                       const float* __restrict__ f1w, const float* __restrict__ f2w,
                       const float* __restrict__ emb,
                       unsigned* XF, unsigned* W1F, unsigned* W2F,
                       float* WS, float* WD,
                       unsigned* FXH, unsigned* FXL, unsigned* F1H, unsigned* F1L,
                       unsigned* F2H, unsigned* F2L, unsigned* EH, unsigned* EL) {
    int b = blockIdx.x, tid = threadIdx.x;
    if (b < PB_X) {
        int idx = b * 256 + tid;
        if (idx >= N_NODES * K2_X) return;
        int m = idx / K2_X, kp = idx - m * K2_X;
        XF[idx] = packHalf2(x[m * F0 + 2 * kp], x[m * F0 + 2 * kp + 1]);
    } else if (b < PB_W1) {
        int idx = (b - PB_X) * 256 + tid;
        if (idx >= H1W * K2_X) return;
        int n = idx / K2_X, kp = idx - n * K2_X;
        float v0, v1;
        if (n < D1) {
            v0 = W1[(2 * kp) * D1 + n];
            v1 = W1[(2 * kp + 1) * D1 + n];
        } else {
            int h = (n - ALS1) % NH1;
            const float* a = (n < ALD1) ? as1 : ad1;
            float s0 = 0.f, s1 = 0.f;
            for (int c = 0; c < F0; c++) {
                float ac = a[h * F0 + c];
                s0 += W1[(2 * kp) * D1 + h * F0 + c] * ac;
                s1 += W1[(2 * kp + 1) * D1 + h * F0 + c] * ac;
            }
            v0 = s0; v1 = s1;
        }
        W1F[idx] = packHalf2(v0, v1);
    } else if (b < PB_W2) {
        int idx = (b - PB_W1) * 256 + tid;
        if (idx >= C2 * K2_D1) return;
        int n = idx / K2_D1, kp = idx - n * K2_D1;
        W2F[idx] = packHalf2(W2[(2 * kp) * C2 + n], W2[(2 * kp + 1) * C2 + n]);
    } else if (b < PB_WS) {
        int idx = (b - PB_W2) * 256 + tid;
        if (idx >= 2 * D1) return;
        int which = idx / D1, j = idx - which * D1;
        const float* a = which ? ad2 : as2;
        float s = 0.f;
#pragma unroll 8
        for (int c = 0; c < C2; c++) s += W2[j * C2 + c] * a[c];
        (which ? WD : WS)[j] = s;
    } else if (b < PB_FXT) {
        int idx = (b - PB_WS) * 256 + tid;
        if (idx >= C2 * K2_XT) return;
        int n = idx / K2_XT, kp = idx - n * K2_XT;
        unsigned H, L;
        split2pack(fxtw[(2 * kp) * C2 + n], fxtw[(2 * kp + 1) * C2 + n], H, L);
        FXH[idx] = H; FXL[idx] = L;
    } else if (b < PB_F1) {
        int idx = (b - PB_FXT) * 256 + tid;
        if (idx >= 1024 * K2_F1) return;
        int n = idx / K2_F1, kp = idx - n * K2_F1;
        unsigned H, L;
        split2pack(f1w[(2 * kp) * 1024 + n], f1w[(2 * kp + 1) * 1024 + n], H, L);
        F1H[idx] = H; F1L[idx] = L;
    } else if (b < PB_F2) {
        int idx = (b - PB_F1) * 256 + tid;
        if (idx >= 256 * K2_F2) return;
        int n = idx / K2_F2, kp = idx - n * K2_F2;
        unsigned H, L;
        split2pack(f2w[(2 * kp) * 256 + n], f2w[(2 * kp + 1) * 256 + n], H, L);
        F2H[idx] = H; F2L[idx] = L;
    } else if (b < PB_EK) {
        int idx = (b - PB_F2) * 256 + tid;
        if (idx >= LOUT * K2_CV) return;
        int l = idx / K2_CV, kp = idx - l * K2_CV;
        int k0 = 2 * kp, k1 = 2 * kp + 1;
        float v0 = emb[(k0 >> 3) * EMBD + (k0 & 7) + l];
        float v1 = emb[(k1 >> 3) * EMBD + (k1 & 7) + l];
        unsigned H, L; split2pack(v0, v1, H, L);
        EH[idx] = H; EL[idx] = L;
    }
}

// ---------------- f16 single-MMA GEMM: pipelined, hoisted addresses ----------------
// kp = tid & 15 is shared by ALL per-thread loads -> ONE k-bound predicate per chunk.
template <bool PACKH1>
__global__ __launch_bounds__(256, 2) void gemm_h(
        int M, int N, int K2,
        const unsigned* __restrict__ AF, int lda2,
        const unsigned* __restrict__ BF,
        float* __restrict__ C, int ldc,
        unsigned* __restrict__ CH,
        int kchunk2) {
    __shared__ unsigned As[128][20];
    __shared__ unsigned Bs[64][20];
    int tid = threadIdx.x;
    int lane = tid & 31, warp = tid >> 5;
    int warp_m = warp & 3, warp_n = warp >> 2;
    int row0 = blockIdx.y * 128, col0 = blockIdx.x * 64;
    int kbeg2 = blockIdx.z * kchunk2;
    int kend2 = min(K2, kbeg2 + kchunk2);
    int lq = lane >> 2, lr = lane & 3;
    int kp = tid & 15;        // k offset shared by all this thread's loads
    int rg = tid >> 4;        // row/col group 0..15

    unsigned sA = (unsigned)__cvta_generic_to_shared(&As[0][0]);
    unsigned sB = (unsigned)__cvta_generic_to_shared(&Bs[0][0]);
    unsigned aOff = (((warp_m << 5) + (lane & 15)) * 20 + ((lane >> 4) << 2)) * 4;
    unsigned bOff = (((warp_n << 5) + (((lane >> 4) & 1) << 3) + (lane & 7)) * 20
                     + (((lane >> 3) & 1) << 2)) * 4;

    float acc[2][4][4] = {};
    unsigned ra[8], rb4[4];
    // 32-bit offsets, row-bound predicates; single base pointer advanced per chunk
    int ofsA[8]; bool vA[8];
    int ofsB[4]; bool vB[4];
#pragma unroll
    for (int i = 0; i < 8; i++) {
        int r = i * 16 + rg;
        vA[i] = (row0 + r < M);
        ofsA[i] = (vA[i] ? (row0 + r) : 0) * lda2 + kp;
    }
#pragma unroll
    for (int i = 0; i < 4; i++) {
        int n = i * 16 + rg;
        vB[i] = (col0 + n < N);
        ofsB[i] = (vB[i] ? (col0 + n) : 0) * K2 + kp;
    }
    const unsigned* pA = AF + kbeg2;
    const unsigned* pB = BF + kbeg2;

    // prologue: chunk 0
    {
        bool kok = (kbeg2 + kp < kend2);
#pragma unroll
        for (int i = 0; i < 8; i++) ra[i] = (kok && vA[i]) ? pA[ofsA[i]] : 0u;
#pragma unroll
        for (int i = 0; i < 4; i++) rb4[i] = (kok && vB[i]) ? pB[ofsB[i]] : 0u;
    }

    for (int p0 = kbeg2; p0 < kend2; p0 += 16) {
#pragma unroll
        for (int i = 0; i < 8; i++) As[i * 16 + rg][kp] = ra[i];
#pragma unroll
        for (int i = 0; i < 4; i++) Bs[i * 16 + rg][kp] = rb4[i];
        __syncthreads();
        int pn = p0 + 16;
        if (pn < kend2) {
            pA += 16; pB += 16;
            bool kok = (pn + kp < kend2);
#pragma unroll
            for (int i = 0; i < 8; i++) ra[i] = (kok && vA[i]) ? pA[ofsA[i]] : 0u;
#pragma unroll
            for (int i = 0; i < 4; i++) rb4[i] = (kok && vB[i]) ? pB[ofsB[i]] : 0u;
        }
#pragma unroll
        for (int s = 0; s < 2; s++) {
            unsigned stepB = s * 32;
            unsigned a[2][4], b[4][2];
#pragma unroll
            for (int mt = 0; mt < 2; mt++) {
                unsigned ao = aOff + mt * (16 * 20 * 4) + stepB;
                ldsm_x4(a[mt][0], a[mt][1], a[mt][2], a[mt][3], sA + ao);
            }
#pragma unroll
            for (int p = 0; p < 2; p++) {
                unsigned bo = bOff + p * (16 * 20 * 4) + stepB;
                ldsm_x4(b[2*p][0], b[2*p][1], b[2*p+1][0], b[2*p+1][1], sB + bo);
            }
#pragma unroll
            for (int mt = 0; mt < 2; mt++)
#pragma unroll
                for (int nt = 0; nt < 4; nt++)
                    mma_f16(acc[mt][nt], a[mt], b[nt]);
        }
        __syncthreads();
    }
    int r_base = row0 + (warp_m << 5) + lq;
    int c_base = col0 + (warp_n << 5) + 2 * lr;
#pragma unroll
    for (int mt = 0; mt < 2; mt++) {
#pragma unroll
        for (int half = 0; half < 2; half++) {
            int r = r_base + mt * 16 + half * 8;
            if (r >= M) continue;
#pragma unroll
            for (int nt = 0; nt < 4; nt++) {
                int c = c_base + nt * 8;   // even
                float v0 = acc[mt][nt][half * 2];
                float v1 = acc[mt][nt][half * 2 + 1];
                if (PACKH1) {
                    long rb = (long)r * H1BW;
                    if (c < ALS1) {
                        CH[rb + (c >> 1)] = packHalf2(v0, v1);
                    } else {
                        if (c < H1W)     CH[rb + 390 + (c - ALS1)]     = __float_as_uint(v0);
                        if (c + 1 < H1W) CH[rb + 390 + (c + 1 - ALS1)] = __float_as_uint(v1);
                    }
                } else {
                    if (c < N)     C[(long)r * ldc + c] = v0;
                    if (c + 1 < N) C[(long)r * ldc + c + 1] = v1;
                }
            }
        }
    }
}

// ---------------- bf16-split GEMM (fc / conv layers) ----------------
template <bool BIAS, bool RELU, bool ATOMIC, bool PACKOUT>
__global__ __launch_bounds__(256, 2) void gemm_p(
        int M, int N, int K2,
        const unsigned* __restrict__ AH, const unsigned* __restrict__ AL, int lda2,
        const unsigned* __restrict__ BH, const unsigned* __restrict__ BL,
        float* __restrict__ C, int ldc,
        unsigned* __restrict__ CH, unsigned* __restrict__ CL, int ldc2,
        const float* __restrict__ bias, int kchunk2) {
    __shared__ unsigned AsH[128][20], AsL[128][20];
    __shared__ unsigned BsH[64][20],  BsL[64][20];
    int tid = threadIdx.x;
    int lane = tid & 31, warp = tid >> 5;
    int warp_m = warp & 3, warp_n = warp >> 2;
    int row0 = blockIdx.y * 128, col0 = blockIdx.x * 64;
    int kbeg2 = blockIdx.z * kchunk2;
    int kend2 = min(K2, kbeg2 + kchunk2);
    int lq = lane >> 2, lr = lane & 3;
    int kp = tid & 15;
    int rg = tid >> 4;

    unsigned sAH = (unsigned)__cvta_generic_to_shared(&AsH[0][0]);
    unsigned sAL = (unsigned)__cvta_generic_to_shared(&AsL[0][0]);
    unsigned sBH = (unsigned)__cvta_generic_to_shared(&BsH[0][0]);
    unsigned sBL = (unsigned)__cvta_generic_to_shared(&BsL[0][0]);
    unsigned aOff = (((warp_m << 5) + (lane & 15)) * 20 + ((lane >> 4) << 2)) * 4;
    unsigned bOff = (((warp_n << 5) + (((lane >> 4) & 1) << 3) + (lane & 7)) * 20
                     + (((lane >> 3) & 1) << 2)) * 4;

    float acc[2][4][4] = {};

    for (int p0 = kbeg2; p0 < kend2; p0 += 16) {
        bool kok = (p0 + kp < kend2);
#pragma unroll
        for (int i = 0; i < 8; i++) {
            int r = i * 16 + rg;
            bool ok = (row0 + r < M) && kok;
            long g = (long)(row0 + r) * lda2 + p0 + kp;
            AsH[r][kp] = ok ? AH[g] : 0u;
            AsL[r][kp] = ok ? AL[g] : 0u;
        }
#pragma unroll
        for (int i = 0; i < 4; i++) {
            int n = i * 16 + rg;
            bool ok = (col0 + n < N) && kok;
            long g = (long)(col0 + n) * K2 + p0 + kp;
            BsH[n][kp] = ok ? BH[g] : 0u;
            BsL[n][kp] = ok ? BL[g] : 0u;
        }
        __syncthreads();
#pragma unroll
        for (int s = 0; s < 2; s++) {
            unsigned stepB = s * 32;
            unsigned aH[2][4], aL[2][4], bH[4][2], bL[4][2];
#pragma unroll
            for (int mt = 0; mt < 2; mt++) {
                unsigned ao = aOff + mt * (16 * 20 * 4) + stepB;
                ldsm_x4(aH[mt][0], aH[mt][1], aH[mt][2], aH[mt][3], sAH + ao);
                ldsm_x4(aL[mt][0], aL[mt][1], aL[mt][2], aL[mt][3], sAL + ao);
            }
#pragma unroll
            for (int p = 0; p < 2; p++) {
                unsigned bo = bOff + p * (16 * 20 * 4) + stepB;
                ldsm_x4(bH[2*p][0], bH[2*p][1], bH[2*p+1][0], bH[2*p+1][1], sBH + bo);
                ldsm_x4(bL[2*p][0], bL[2*p][1], bL[2*p+1][0], bL[2*p+1][1], sBL + bo);
            }
#pragma unroll
            for (int mt = 0; mt < 2; mt++)
#pragma unroll
                for (int nt = 0; nt < 4; nt++) {
                    mma_bf16(acc[mt][nt], aH[mt], bH[nt]);
                    mma_bf16(acc[mt][nt], aH[mt], bL[nt]);
                    mma_bf16(acc[mt][nt], aL[mt], bH[nt]);
                }
        }
        __syncthreads();
    }
    int r_base = row0 + (warp_m << 5) + lq;
    int c_base = col0 + (warp_n << 5) + 2 * lr;
#pragma unroll
    for (int mt = 0; mt < 2; mt++) {
#pragma unroll
        for (int half = 0; half < 2; half++) {
            int r = r_base + mt * 16 + half * 8;
            if (r >= M) continue;
#pragma unroll
            for (int nt = 0; nt < 4; nt++) {
                int c = c_base + nt * 8;
                if (PACKOUT) {
                    float v0 = acc[mt][nt][half * 2];
                    float v1 = acc[mt][nt][half * 2 + 1];
                    if (BIAS) { v0 += bias[c]; v1 += bias[c + 1]; }
                    if (RELU) { v0 = fmaxf(v0, 0.f); v1 = fmaxf(v1, 0.f); }
                    if (c + 1 < N) {
                        unsigned H, L;
                        split2pack(v0, v1, H, L);
                        CH[(long)r * ldc2 + (c >> 1)] = H;
                        CL[(long)r * ldc2 + (c >> 1)] = L;
                    }
                } else {
#pragma unroll
                    for (int j = 0; j < 2; j++) {
                        int cc = c + j;
                        if (cc >= N) continue;
                        float v = acc[mt][nt][half * 2 + j];
                        if (ATOMIC) {
                            atomicAdd(&C[(long)r * ldc + cc], v);
                        } else {
                            if (BIAS) v += bias[cc];
                            if (RELU) v = fmaxf(v, 0.f);
                            C[(long)r * ldc + cc] = v;
                        }
                    }
                }
            }
        }
    }
}

__global__ void bias_init_k(float* C, int ldc, int M, int N, const float* __restrict__ bias) {
    int idx = blockIdx.x * blockDim.x + threadIdx.x;
    if (idx < M * N) { int r = idx / N, c = idx % N; C[(long)r * ldc + c] = bias[c]; }
}

// ---------------- GAT layer 1: warp/node, uint2 gather + uint2 pack out ----------------
__global__ __launch_bounds__(256) void agg1_k(
        const unsigned* __restrict__ h1b, const int* __restrict__ off,
        const int* __restrict__ srcs, const float* __restrict__ b1,
        const float* __restrict__ ws, const float* __restrict__ wd,
        unsigned* __restrict__ outF,
        float* __restrict__ als2, float* __restrict__ ald2) {
    int gw = (blockIdx.x * blockDim.x + threadIdx.x) >> 5;
    int lane = threadIdx.x & 31;
    if (gw >= N_NODES) return;
    int i = gw;
    int base = off[i];
    int deg = off[i + 1] - base;
    float aldi = (lane < NH1) ? __uint_as_float(h1b[(long)i * H1BW + 400 + lane]) : 0.f;
    float denom = 0.f;
    // 7 uint2 slots per lane: pair indices 2*p2, 2*p2+1 where p2 = j*32+lane (<195)
    float ax0[7], ay0[7], ax1[7], ay1[7];
    int h0[7], h1i[7];
    bool pv[7];
#pragma unroll
    for (int j = 0; j < 7; j++) {
        ax0[j] = ay0[j] = ax1[j] = ay1[j] = 0.f;
        int p2 = j * 32 + lane;
        pv[j] = (p2 < 195);
        int p2c = pv[j] ? p2 : 194;
        h0[j]  = (2 * p2c) / 39;
        h1i[j] = (2 * p2c + 1) / 39;
    }
    for (int e = 0; e < deg; e++) {
        int src = srcs[base + e];
        const unsigned* hr = h1b + (long)src * H1BW;
        const uint2* hr2 = reinterpret_cast<const uint2*>(hr);
        float we = 0.f;
        if (lane < NH1) {
            float l = __uint_as_float(hr[390 + lane]) + aldi;
            l = l > 0.f ? l : 0.2f * l;
            we = expf(l);
            denom += we;
        }
#pragma unroll
        for (int j = 0; j < 7; j++) {
            int p2 = j * 32 + lane;
            uint2 u = pv[j] ? hr2[p2] : make_uint2(0u, 0u);
            float w0 = __shfl_sync(0xffffffffu, we, h0[j]);
            float w1 = __shfl_sync(0xffffffffu, we, h1i[j]);
            float2 f0 = __half22float2(*reinterpret_cast<const __half2*>(&u.x));
            float2 f1 = __half22float2(*reinterpret_cast<const __half2*>(&u.y));
            ax0[j] += w0 * f0.x; ay0[j] += w0 * f0.y;
            ax1[j] += w1 * f1.x; ay1[j] += w1 * f1.y;
        }
    }
    float sinv = 1.f / (denom + 1e-16f);  // valid in lanes 0..9
    float cs = 0.f, cd = 0.f;
    uint2* out2 = reinterpret_cast<uint2*>(outF + (long)i * K2_D1);
#pragma unroll
    for (int j = 0; j < 7; j++) {
        int p2 = j * 32 + lane;
        float sv0 = __shfl_sync(0xffffffffu, sinv, h0[j]);
        float sv1 = __shfl_sync(0xffffffffu, sinv, h1i[j]);
        if (pv[j]) {
            int cch = 4 * p2;   // first channel index
            float v0 = ax0[j] * sv0 + b1[cch];     v0 = v0 > 0.f ? v0 : expf(v0) - 1.f;
            float v1 = ay0[j] * sv0 + b1[cch + 1]; v1 = v1 > 0.f ? v1 : expf(v1) - 1.f;
            float v2 = ax1[j] * sv1 + b1[cch + 2]; v2 = v2 > 0.f ? v2 : expf(v2) - 1.f;
            float v3 = ay1[j] * sv1 + b1[cch + 3]; v3 = v3 > 0.f ? v3 : expf(v3) - 1.f;
            cs += v0 * ws[cch] + v1 * ws[cch + 1] + v2 * ws[cch + 2] + v3 * ws[cch + 3];
            cd += v0 * wd[cch] + v1 * wd[cch + 1] + v2 * wd[cch + 2] + v3 * wd[cch + 3];
            uint2 o;
            o.x = packHalf2(v0, v1);
            o.y = packHalf2(v2, v3);
            out2[p2] = o;
        }
    }
#pragma unroll
    for (int o = 16; o; o >>= 1) {
        cs += __shfl_down_sync(0xffffffffu, cs, o);
        cd += __shfl_down_sync(0xffffffffu, cd, o);
    }
    if (lane == 0) { als2[i] = cs; ald2[i] = cd; }
}

// ---------------- GAT layer 2: warp/node, float4 gather ----------------
__global__ __launch_bounds__(256) void agg2_k(
        const float* __restrict__ h2, const float* __restrict__ als,
        const float* __restrict__ ald, const int* __restrict__ off,
        const int* __restrict__ srcs, const float* __restrict__ b2,
        float* __restrict__ out) {
    int gw = (blockIdx.x * blockDim.x + threadIdx.x) >> 5;
    int lane = threadIdx.x & 31;
    if (gw >= N_NODES) return;
    int i = gw;
    int base = off[i];
    int deg = off[i + 1] - base;
    float aldi = ald[i];
    float denom = 0.f;
    float a0 = 0.f, a1 = 0.f, a2 = 0.f, a3 = 0.f;
    for (int e = 0; e < deg; e++) {
        int src = srcs[base + e];
        float l = als[src] + aldi;
        l = l > 0.f ? l : 0.2f * l;
        float w = expf(l);
        denom += w;
        const float4* hr4 = reinterpret_cast<const float4*>(h2 + (long)src * C2);
        float4 v = hr4[lane];   // channels 4*lane .. 4*lane+3
        a0 += w * v.x; a1 += w * v.y; a2 += w * v.z; a3 += w * v.w;
    }
    float sinv = 1.f / (denom + 1e-16f);
    int c = 4 * lane;
    float4 o;
    o.x = fmaxf(a0 * sinv + b2[c], 0.f);
    o.y = fmaxf(a1 * sinv + b2[c + 1], 0.f);
    o.z = fmaxf(a2 * sinv + b2[c + 2], 0.f);
    o.w = fmaxf(a3 * sinv + b2[c + 3], 0.f);
    reinterpret_cast<float4*>(out + (long)i * C2)[lane] = o;
}

// ---------------- starts ----------------
__global__ void starts_k(const int* __restrict__ batch, int* starts) {
    int i = blockIdx.x * blockDim.x + threadIdx.x;
    if (i >= N_NODES) return;
    if (i == 0) starts[0] = 0;
    else if (batch[i] != batch[i - 1]) starts[batch[i]] = i;
    if (i == N_NODES - 1) starts[BATCH] = N_NODES;
}

// ---------------- fused pool + fc_g1 + pack ----------------
__global__ void poolfc_k(const float* __restrict__ o2, const int* __restrict__ starts,
                         const float* __restrict__ fgw, const float* __restrict__ fgb,
                         unsigned* __restrict__ XH, unsigned* __restrict__ XL) {
    int b = blockIdx.x, c = threadIdx.x;  // 128 threads
    __shared__ float pool[C2];
    int s = starts[b], e = starts[b + 1];
    float m = -1e30f;
    for (int r = s; r < e; r++) m = fmaxf(m, o2[(long)r * C2 + c]);
    pool[c] = m;
    __syncthreads();
    float acc = fgb[c];
#pragma unroll 8
    for (int k = 0; k < C2; k++) acc += pool[k] * fgw[k * C2 + c];
    acc = fmaxf(acc, 0.f);
    float p = __shfl_xor_sync(0xffffffffu, acc, 1);
    if (!(c & 1)) {
        unsigned H, L; split2pack(acc, p, H, L);
        XH[b * K2_F1 + (c >> 1)] = H;
        XL[b * K2_F1 + (c >> 1)] = L;
    }
}

// ---------------- conv branch ----------------
__global__ void scatterA_k(const int* __restrict__ target, const float* __restrict__ cw,
                           unsigned* __restrict__ AH, unsigned* __restrict__ AL) {
    int b = blockIdx.x, tid = threadIdx.x;
    __shared__ float Ash[NF * VOCAB * KW];
    for (int i = tid; i < NF * VOCAB * KW; i += 256) Ash[i] = 0.f;
    __syncthreads();
    int o = tid >> 3, k = tid & 7;
    const float* wrow = cw + o * (SEQ * KW) + k;
    float* arow = Ash + o * (VOCAB * KW) + k;
    for (int s = 0; s < SEQ; s++) {
        int v = target[b * SEQ + s];
        arow[v * KW] += wrow[s * KW];
    }
    __syncthreads();
    for (int i = tid; i < NF * K2_CV; i += 256) {
        int o2_ = i / K2_CV, kp = i - o2_ * K2_CV;
        unsigned H, L;
        split2pack(Ash[o2_ * (VOCAB * KW) + 2 * kp], Ash[o2_ * (VOCAB * KW) + 2 * kp + 1], H, L);
        long g = ((long)b * NF + o2_) * K2_CV + kp;
        AH[g] = H; AL[g] = L;
    }
}
__global__ void conv_epi_k(const float* __restrict__ c, const float* __restrict__ cb,
                           unsigned* __restrict__ outH, unsigned* __restrict__ outL) {
    int idx = blockIdx.x * blockDim.x + threadIdx.x;
    if (idx >= BATCH * NF * LOUT) return;
    int o = (idx / LOUT) & (NF - 1);
    float v = fmaxf(c[idx] + cb[o], 0.f);
    float p = __shfl_xor_sync(0xffffffffu, v, 1);
    if (!(idx & 1)) {
        unsigned H, L; split2pack(v, p, H, L);
        outH[idx >> 1] = H; outL[idx >> 1] = L;
    }
}
__global__ void xtpack_k(const float* __restrict__ xt, unsigned* __restrict__ XH, unsigned* __restrict__ XL) {
    int idx = blockIdx.x * blockDim.x + threadIdx.x;
    if (idx >= BATCH * 64) return;
    int r = idx >> 6, p = idx & 63;
    unsigned H, L;
    split2pack(xt[r * C2 + 2 * p], xt[r * C2 + 2 * p + 1], H, L);
    XH[r * K2_F1 + 64 + p] = H; XL[r * K2_F1 + 64 + p] = L;
}

// ---------------- final ----------------
__global__ void final_k(const float* __restrict__ x, const float* __restrict__ w,
                        const float* __restrict__ b, float* __restrict__ y) {
    int gw = (blockIdx.x * blockDim.x + threadIdx.x) >> 5;
    int lane = threadIdx.x & 31;
    if (gw >= BATCH) return;
    float s = 0.f;
#pragma unroll
    for (int j = lane; j < 256; j += 32) s += x[gw * 256 + j] * w[j];
#pragma unroll
    for (int o = 16; o; o >>= 1) s += __shfl_down_sync(0xffffffffu, s, o);
    if (lane == 0) y[gw] = s + b[0];
}

// ---------------- host ----------------
extern "C" void kernel_launch(void* const* d_in, const int* in_sizes, int n_in,
                              void* d_out, int out_size) {
    const float* x       = (const float*)d_in[0];
    const int*   ei      = (const int*)d_in[1];
    const int*   batch   = (const int*)d_in[2];
    const int*   target  = (const int*)d_in[3];
    const float* W1      = (const float*)d_in[4];
    const float* a_src1  = (const float*)d_in[5];
    const float* a_dst1  = (const float*)d_in[6];
    const float* b1      = (const float*)d_in[7];
    const float* W2      = (const float*)d_in[8];
    const float* a_src2  = (const float*)d_in[9];
    const float* a_dst2  = (const float*)d_in[10];
    const float* b2      = (const float*)d_in[11];
    const float* fc_g1_w = (const float*)d_in[12];
    const float* fc_g1_b = (const float*)d_in[13];
    const float* emb     = (const float*)d_in[14];
    const float* conv_w  = (const float*)d_in[15];
    const float* conv_b  = (const float*)d_in[16];
    const float* fc_xt_w = (const float*)d_in[17];
    const float* fc_xt_b = (const float*)d_in[18];
    const float* fc1_w   = (const float*)d_in[19];
    const float* fc1_b   = (const float*)d_in[20];
    const float* fc2_w   = (const float*)d_in[21];
    const float* fc2_b   = (const float*)d_in[22];
    const float* out_w   = (const float*)d_in[23];
    const float* out_b   = (const float*)d_in[24];
    float* y = (float*)d_out;
    int E = in_sizes[1] / 2;

    float *h2p, *o2p, *convp, *xtp, *f2p, *wsp, *wdp, *als2p, *ald2p;
    unsigned *h1bp, *xFp, *w1Fp, *h1eFp, *w2Fp;
    unsigned *AHp, *ALp, *EkHp, *EkLp;
    unsigned *cvHp, *cvLp, *fxtHp, *fxtLp, *xcHp, *xcLp, *f1wHp, *f1wLp;
    unsigned *f1Hp, *f1Lp, *f2wHp, *f2wLp;
    int *degp, *offp, *curp, *srcsp, *startsp;
    cudaGetSymbolAddress((void**)&h1bp, g_h1b);
    cudaGetSymbolAddress((void**)&h2p, g_h2);
    cudaGetSymbolAddress((void**)&o2p, g_o2);
    cudaGetSymbolAddress((void**)&convp, g_conv);
    cudaGetSymbolAddress((void**)&xtp, g_xt);
    cudaGetSymbolAddress((void**)&f2p, g_f2);
    cudaGetSymbolAddress((void**)&wsp, g_ws);   cudaGetSymbolAddress((void**)&wdp, g_wd);
    cudaGetSymbolAddress((void**)&als2p, g_als2); cudaGetSymbolAddress((void**)&ald2p, g_ald2);
    cudaGetSymbolAddress((void**)&xFp, g_xF);
    cudaGetSymbolAddress((void**)&w1Fp, g_w1F);
    cudaGetSymbolAddress((void**)&h1eFp, g_h1eF);
    cudaGetSymbolAddress((void**)&w2Fp, g_w2F);
    cudaGetSymbolAddress((void**)&AHp, g_AH);   cudaGetSymbolAddress((void**)&ALp, g_AL);
    cudaGetSymbolAddress((void**)&EkHp, g_EkH); cudaGetSymbolAddress((void**)&EkLp, g_EkL);
    cudaGetSymbolAddress((void**)&cvHp, g_cvH); cudaGetSymbolAddress((void**)&cvLp, g_cvL);
    cudaGetSymbolAddress((void**)&fxtHp, g_fxtH); cudaGetSymbolAddress((void**)&fxtLp, g_fxtL);
    cudaGetSymbolAddress((void**)&xcHp, g_xcH); cudaGetSymbolAddress((void**)&xcLp, g_xcL);
    cudaGetSymbolAddress((void**)&f1wHp, g_f1wH); cudaGetSymbolAddress((void**)&f1wLp, g_f1wL);
    cudaGetSymbolAddress((void**)&f1Hp, g_f1H); cudaGetSymbolAddress((void**)&f1Lp, g_f1L);
    cudaGetSymbolAddress((void**)&f2wHp, g_f2wH); cudaGetSymbolAddress((void**)&f2wLp, g_f2wL);
    cudaGetSymbolAddress((void**)&degp, g_deg);
    cudaGetSymbolAddress((void**)&offp, g_off);
    cudaGetSymbolAddress((void**)&curp, g_cur);
    cudaGetSymbolAddress((void**)&srcsp, g_srcs);
    cudaGetSymbolAddress((void**)&startsp, g_starts);

    static cudaStream_t s1 = nullptr, s2 = nullptr;
    static cudaEvent_t evRoot = nullptr, evPrep = nullptr, evCSR = nullptr, evConv = nullptr;
    if (!s1) {
        cudaStreamCreateWithFlags(&s1, cudaStreamNonBlocking);
        cudaStreamCreateWithFlags(&s2, cudaStreamNonBlocking);
        cudaEventCreateWithFlags(&evRoot, cudaEventDisableTiming);
        cudaEventCreateWithFlags(&evPrep, cudaEventDisableTiming);
        cudaEventCreateWithFlags(&evCSR, cudaEventDisableTiming);
        cudaEventCreateWithFlags(&evConv, cudaEventDisableTiming);
    }

    // fork
    cudaEventRecord(evRoot, 0);
    cudaStreamWaitEvent(s1, evRoot, 0);
    cudaStreamWaitEvent(s2, evRoot, 0);

    // #1 prep (s0); CSR on s1; #4 on s0 = GEMM1 -> ncu window
    prep_k<<<PB_EK, 256>>>(x, W1, a_src1, a_dst1, W2, a_src2, a_dst2,
                           fc_xt_w, fc1_w, fc2_w, emb,
                           xFp, w1Fp, w2Fp, wsp, wdp,
                           fxtHp, fxtLp, f1wHp, f1wLp,
                           f2wHp, f2wLp, EkHp, EkLp);
    cudaEventRecord(evPrep, 0);
    deg_init_k<<<(N_NODES + 255) / 256, 256, 0, s1>>>(degp);
    hist_k<<<(E + 255) / 256, 256, 0, s1>>>(ei, degp, E);
    {   // GEMM1 (f16, pipelined, hoisted): [50000, 800] -> hybrid packed h1b
        dim3 g((H1W + 63) / 64, (N_NODES + 127) / 128);
        gemm_h<true><<<g, 256>>>(N_NODES, H1W, K2_X,
            xFp, K2_X, w1Fp, nullptr, 0, h1bp, K2_X);
    }
    scan_k<<<1, 1024, 0, s1>>>(degp, offp, N_NODES);
    selfloop_k<<<(N_NODES + 255) / 256, 256, 0, s1>>>(offp, curp, srcsp);
    fill_k<<<(E + 255) / 256, 256, 0, s1>>>(ei, curp, srcsp, E);
    starts_k<<<(N_NODES + 255) / 256, 256, 0, s1>>>(batch, startsp);
    cudaEventRecord(evCSR, s1);

    // s2: conv branch
    scatterA_k<<<BATCH, 256, 0, s2>>>(target, conv_w, AHp, ALp);
    cudaStreamWaitEvent(s2, evPrep, 0);
    {
        dim3 g((LOUT + 63) / 64, (BATCH * NF + 127) / 128);
        gemm_p<false, false, false, false><<<g, 256, 0, s2>>>(BATCH * NF, LOUT, K2_CV,
            AHp, ALp, K2_CV, EkHp, EkLp, convp, LOUT, nullptr, nullptr, 0, nullptr, K2_CV);
    }
    conv_epi_k<<<(BATCH * NF * LOUT + 255) / 256, 256, 0, s2>>>(convp, conv_b, cvHp, cvLp);
    bias_init_k<<<(BATCH * C2 + 255) / 256, 256, 0, s2>>>(xtp, C2, BATCH, C2, fc_xt_b);
    {
        dim3 g(2, 4, 8);
        gemm_p<false, false, true, false><<<g, 256, 0, s2>>>(BATCH, C2, K2_XT,
            cvHp, cvLp, K2_XT, fxtHp, fxtLp, xtp, C2, nullptr, nullptr, 0, nullptr, 242);
    }
    xtpack_k<<<(BATCH * 64 + 255) / 256, 256, 0, s2>>>(xtp, xcHp, xcLp);
    cudaEventRecord(evConv, s2);

    // s0 main chain
    cudaStreamWaitEvent(0, evCSR, 0);
    agg1_k<<<(N_NODES * 32 + 255) / 256, 256>>>(h1bp, offp, srcsp, b1, wsp, wdp, h1eFp, als2p, ald2p);
    {   // GEMM2 (f16, pipelined, hoisted): [50000, 128]
        dim3 g(2, (N_NODES + 127) / 128);
        gemm_h<false><<<g, 256>>>(N_NODES, C2, K2_D1,
            h1eFp, K2_D1, w2Fp, h2p, C2, nullptr, K2_D1);
    }
    agg2_k<<<(N_NODES * 32 + 255) / 256, 256>>>(h2p, als2p, ald2p, offp, srcsp, b2, o2p);
    poolfc_k<<<BATCH, C2>>>(o2p, startsp, fc_g1_w, fc_g1_b, xcHp, xcLp);
    cudaStreamWaitEvent(0, evConv, 0);
    {   // fc1
        dim3 g(16, 4);
        gemm_p<true, true, false, true><<<g, 256>>>(BATCH, 1024, K2_F1,
            xcHp, xcLp, K2_F1, f1wHp, f1wLp, nullptr, 0, f1Hp, f1Lp, K2_F2, fc1_b, K2_F1);
    }
    {   // fc2
        dim3 g(4, 4);
        gemm_p<true, true, false, false><<<g, 256>>>(BATCH, 256, K2_F2,
            f1Hp, f1Lp, K2_F2, f2wHp, f2wLp, f2p, 256, nullptr, nullptr, 0, fc2_b, K2_F2);
    }
    final_k<<<64, 256>>>(f2p, out_w, out_b, y);
}

// round 14
// speedup vs baseline: 1.0562x; 1.0562x over previous
#include <cuda_runtime.h>
#include <cuda_bf16.h>
#include <cuda_fp16.h>
#include <math.h>

#define N_NODES 50000
#define BATCH   512
#define F0      78
#define NH1     10
#define D1      780
#define C2      128
#define EMBD    128
#define SEQ     1000
#define VOCAB   26
#define KW      8
#define NF      32
#define LOUT    121
#define E_TOT   250000

#define H1W     800
#define ALS1    780
#define ALD1    790
#define H1BW    416
#define K2_X    39
#define K2_D1   390
#define K2_CV   104
#define K2_XT   1936
#define K2_F1   128
#define K2_F2   512

// ---------------- scratch ----------------
__device__ unsigned g_h1b  [N_NODES * H1BW];
__device__ unsigned g_xF   [N_NODES * K2_X];
__device__ unsigned g_w1F  [H1W * K2_X];
__device__ unsigned g_h1eF [N_NODES * K2_D1];
__device__ unsigned g_w2F  [C2 * K2_D1];
__device__ float    g_ws   [D1], g_wd[D1];
__device__ float    g_als2 [N_NODES], g_ald2[N_NODES];
__device__ float    g_h2   [N_NODES * C2];
__device__ float    g_o2   [N_NODES * C2];
__device__ unsigned g_AH   [BATCH * NF * K2_CV], g_AL [BATCH * NF * K2_CV];
__device__ unsigned g_EkH  [LOUT * K2_CV],     g_EkL  [LOUT * K2_CV];
__device__ float    g_conv [BATCH * NF * LOUT];
__device__ unsigned g_cvH  [BATCH * K2_XT],    g_cvL  [BATCH * K2_XT];
__device__ unsigned g_fxtH [C2 * K2_XT],       g_fxtL [C2 * K2_XT];
__device__ float    g_xt   [BATCH * C2];
__device__ unsigned g_xcH  [BATCH * K2_F1],    g_xcL  [BATCH * K2_F1];
__device__ unsigned g_f1wH [1024 * K2_F1],     g_f1wL [1024 * K2_F1];
__device__ unsigned g_f1H  [BATCH * K2_F2],    g_f1L  [BATCH * K2_F2];
__device__ unsigned g_f2wH [256 * K2_F2],      g_f2wL [256 * K2_F2];
__device__ float    g_f2   [BATCH * 256];
__device__ int g_deg[N_NODES], g_off[N_NODES + 1], g_cur[N_NODES];
__device__ int g_srcs[E_TOT], g_starts[BATCH + 1];

// ---------------- helpers ----------------
__device__ __forceinline__ void bf16_split(float v, unsigned short& h, unsigned short& l) {
    __nv_bfloat16 hb = __float2bfloat16(v);
    float r = v - __bfloat162float(hb);
    __nv_bfloat16 lb = __float2bfloat16(r);
    h = __bfloat16_as_ushort(hb);
    l = __bfloat16_as_ushort(lb);
}
__device__ __forceinline__ void split2pack(float v0, float v1, unsigned& H, unsigned& L) {
    unsigned short h0, l0, h1, l1;
    bf16_split(v0, h0, l0);
    bf16_split(v1, h1, l1);
    H = ((unsigned)h1 << 16) | h0;
    L = ((unsigned)l1 << 16) | l0;
}
__device__ __forceinline__ unsigned packHalf2(float v0, float v1) {
    __half2 h = __floats2half2_rn(v0, v1);
    return *reinterpret_cast<unsigned*>(&h);
}
__device__ __forceinline__ void mma_bf16(float* c, const unsigned* a, const unsigned* b) {
    asm volatile(
        "mma.sync.aligned.m16n8k16.row.col.f32.bf16.bf16.f32 "
        "{%0,%1,%2,%3}, {%4,%5,%6,%7}, {%8,%9}, {%0,%1,%2,%3};\n"
        : "+f"(c[0]), "+f"(c[1]), "+f"(c[2]), "+f"(c[3])
        : "r"(a[0]), "r"(a[1]), "r"(a[2]), "r"(a[3]), "r"(b[0]), "r"(b[1]));
}
__device__ __forceinline__ void mma_f16(float* c, const unsigned* a, const unsigned* b) {
    asm volatile(
        "mma.sync.aligned.m16n8k16.row.col.f32.f16.f16.f32 "
        "{%0,%1,%2,%3}, {%4,%5,%6,%7}, {%8,%9}, {%0,%1,%2,%3};\n"
        : "+f"(c[0]), "+f"(c[1]), "+f"(c[2]), "+f"(c[3])
        : "r"(a[0]), "r"(a[1]), "r"(a[2]), "r"(a[3]), "r"(b[0]), "r"(b[1]));
}
__device__ __forceinline__ void ldsm_x4(unsigned& r0, unsigned& r1, unsigned& r2, unsigned& r3,
                                        unsigned addr) {
    asm volatile("ldmatrix.sync.aligned.m8n8.x4.shared.b16 {%0,%1,%2,%3}, [%4];"
        : "=r"(r0), "=r"(r1), "=r"(r2), "=r"(r3) : "r"(addr));
}

// ---------------- CSR build ----------------
__global__ void deg_init_k(int* deg) {
    int i = blockIdx.x * blockDim.x + threadIdx.x;
    if (i < N_NODES) deg[i] = 1;
}
__global__ void hist_k(const int* __restrict__ ei, int* deg, int E) {
    int e = blockIdx.x * blockDim.x + threadIdx.x;
    if (e < E) atomicAdd(&deg[ei[E + e]], 1);
}
__global__ void scan_k(const int* __restrict__ deg, int* off, int n) {
    __shared__ int wsum[32];
    __shared__ int carry_s;
    int tid = threadIdx.x, lane = tid & 31, w = tid >> 5;
    if (tid == 0) { carry_s = 0; off[0] = 0; }
    __syncthreads();
    for (int base = 0; base < n; base += 1024) {
        int x = (base + tid < n) ? deg[base + tid] : 0;
#pragma unroll
        for (int o = 1; o < 32; o <<= 1) {
            int y = __shfl_up_sync(0xffffffffu, x, o);
            if (lane >= o) x += y;
        }
        if (lane == 31) wsum[w] = x;
        __syncthreads();
        if (w == 0) {
            int s = wsum[lane];
#pragma unroll
            for (int o = 1; o < 32; o <<= 1) {
                int y = __shfl_up_sync(0xffffffffu, s, o);
                if (lane >= o) s += y;
            }
            wsum[lane] = s;
        }
        __syncthreads();
        int woff = (w == 0) ? 0 : wsum[w - 1];
        if (base + tid < n) off[base + tid + 1] = carry_s + woff + x;
        __syncthreads();
        if (tid == 0) carry_s += wsum[31];
        __syncthreads();
    }
}
__global__ void selfloop_k(const int* __restrict__ off, int* cur, int* srcs) {
    int i = blockIdx.x * blockDim.x + threadIdx.x;
    if (i < N_NODES) { int b = off[i]; srcs[b] = i; cur[i] = b + 1; }
}
__global__ void fill_k(const int* __restrict__ ei, int* cur, int* srcs, int E) {
    int e = blockIdx.x * blockDim.x + threadIdx.x;
    if (e < E) {
        int d = ei[E + e];
        int p = atomicAdd(&cur[d], 1);
        srcs[p] = ei[e];
    }
}

// ---------------- mega prep ----------------
#define PB_X   7618
#define PB_W1  (PB_X + 122)
#define PB_W2  (PB_W1 + 195)
#define PB_WS  (PB_W2 + 7)
#define PB_FXT (PB_WS + 968)
#define PB_F1  (PB_FXT + 512)
#define PB_F2  (PB_F1 + 512)
#define PB_EK  (PB_F2 + 50)
__global__ void prep_k(const float* __restrict__ x,
                       const float* __restrict__ W1, const float* __restrict__ as1, const float* __restrict__ ad1,
                       const float* __restrict__ W2, const float* __restrict__ as2, const float* __restrict__ ad2,
                       const float* __restrict__ fxtw,
                       const float* __restrict__ f1w, const float* __restrict__ f2w,
                       const float* __restrict__ emb,
                       unsigned* XF, unsigned* W1F, unsigned* W2F,
                       float* WS, float* WD,
                       unsigned* FXH, unsigned* FXL, unsigned* F1H, unsigned* F1L,
                       unsigned* F2H, unsigned* F2L, unsigned* EH, unsigned* EL) {
    int b = blockIdx.x, tid = threadIdx.x;
    if (b < PB_X) {
        int idx = b * 256 + tid;
        if (idx >= N_NODES * K2_X) return;
        int m = idx / K2_X, kp = idx - m * K2_X;
        XF[idx] = packHalf2(x[m * F0 + 2 * kp], x[m * F0 + 2 * kp + 1]);
    } else if (b < PB_W1) {
        int idx = (b - PB_X) * 256 + tid;
        if (idx >= H1W * K2_X) return;
        int n = idx / K2_X, kp = idx - n * K2_X;
        float v0, v1;
        if (n < D1) {
            v0 = W1[(2 * kp) * D1 + n];
            v1 = W1[(2 * kp + 1) * D1 + n];
        } else {
            int h = (n - ALS1) % NH1;
            const float* a = (n < ALD1) ? as1 : ad1;
            float s0 = 0.f, s1 = 0.f;
            for (int c = 0; c < F0; c++) {
                float ac = a[h * F0 + c];
                s0 += W1[(2 * kp) * D1 + h * F0 + c] * ac;
                s1 += W1[(2 * kp + 1) * D1 + h * F0 + c] * ac;
            }
            v0 = s0; v1 = s1;
        }
        W1F[idx] = packHalf2(v0, v1);
    } else if (b < PB_W2) {
        int idx = (b - PB_W1) * 256 + tid;
        if (idx >= C2 * K2_D1) return;
        int n = idx / K2_D1, kp = idx - n * K2_D1;
        W2F[idx] = packHalf2(W2[(2 * kp) * C2 + n], W2[(2 * kp + 1) * C2 + n]);
    } else if (b < PB_WS) {
        int idx = (b - PB_W2) * 256 + tid;
        if (idx >= 2 * D1) return;
        int which = idx / D1, j = idx - which * D1;
        const float* a = which ? ad2 : as2;
        float s = 0.f;
#pragma unroll 8
        for (int c = 0; c < C2; c++) s += W2[j * C2 + c] * a[c];
        (which ? WD : WS)[j] = s;
    } else if (b < PB_FXT) {
        int idx = (b - PB_WS) * 256 + tid;
        if (idx >= C2 * K2_XT) return;
        int n = idx / K2_XT, kp = idx - n * K2_XT;
        unsigned H, L;
        split2pack(fxtw[(2 * kp) * C2 + n], fxtw[(2 * kp + 1) * C2 + n], H, L);
        FXH[idx] = H; FXL[idx] = L;
    } else if (b < PB_F1) {
        int idx = (b - PB_FXT) * 256 + tid;
        if (idx >= 1024 * K2_F1) return;
        int n = idx / K2_F1, kp = idx - n * K2_F1;
        unsigned H, L;
        split2pack(f1w[(2 * kp) * 1024 + n], f1w[(2 * kp + 1) * 1024 + n], H, L);
        F1H[idx] = H; F1L[idx] = L;
    } else if (b < PB_F2) {
        int idx = (b - PB_F1) * 256 + tid;
        if (idx >= 256 * K2_F2) return;
        int n = idx / K2_F2, kp = idx - n * K2_F2;
        unsigned H, L;
        split2pack(f2w[(2 * kp) * 256 + n], f2w[(2 * kp + 1) * 256 + n], H, L);
        F2H[idx] = H; F2L[idx] = L;
    } else if (b < PB_EK) {
        int idx = (b - PB_F2) * 256 + tid;
        if (idx >= LOUT * K2_CV) return;
        int l = idx / K2_CV, kp = idx - l * K2_CV;
        int k0 = 2 * kp, k1 = 2 * kp + 1;
        float v0 = emb[(k0 >> 3) * EMBD + (k0 & 7) + l];
        float v1 = emb[(k1 >> 3) * EMBD + (k1 & 7) + l];
        unsigned H, L; split2pack(v0, v1, H, L);
        EH[idx] = H; EL[idx] = L;
    }
}

// ---------------- f16 single-MMA GEMM: pipelined, hoisted addresses ----------------
template <bool PACKH1>
__global__ __launch_bounds__(256, 2) void gemm_h(
        int M, int N, int K2,
        const unsigned* __restrict__ AF, int lda2,
        const unsigned* __restrict__ BF,
        float* __restrict__ C, int ldc,
        unsigned* __restrict__ CH,
        int kchunk2) {
    __shared__ unsigned As[128][20];
    __shared__ unsigned Bs[64][20];
    int tid = threadIdx.x;
    int lane = tid & 31, warp = tid >> 5;
    int warp_m = warp & 3, warp_n = warp >> 2;
    int row0 = blockIdx.y * 128, col0 = blockIdx.x * 64;
    int kbeg2 = blockIdx.z * kchunk2;
    int kend2 = min(K2, kbeg2 + kchunk2);
    int lq = lane >> 2, lr = lane & 3;
    int kp = tid & 15;
    int rg = tid >> 4;

    unsigned sA = (unsigned)__cvta_generic_to_shared(&As[0][0]);
    unsigned sB = (unsigned)__cvta_generic_to_shared(&Bs[0][0]);
    unsigned aOff = (((warp_m << 5) + (lane & 15)) * 20 + ((lane >> 4) << 2)) * 4;
    unsigned bOff = (((warp_n << 5) + (((lane >> 4) & 1) << 3) + (lane & 7)) * 20
                     + (((lane >> 3) & 1) << 2)) * 4;

    float acc[2][4][4] = {};
    unsigned ra[8], rb4[4];
    int ofsA[8]; bool vA[8];
    int ofsB[4]; bool vB[4];
#pragma unroll
    for (int i = 0; i < 8; i++) {
        int r = i * 16 + rg;
        vA[i] = (row0 + r < M);
        ofsA[i] = (vA[i] ? (row0 + r) : 0) * lda2 + kp;
    }
#pragma unroll
    for (int i = 0; i < 4; i++) {
        int n = i * 16 + rg;
        vB[i] = (col0 + n < N);
        ofsB[i] = (vB[i] ? (col0 + n) : 0) * K2 + kp;
    }
    const unsigned* pA = AF + kbeg2;
    const unsigned* pB = BF + kbeg2;

    {
        bool kok = (kbeg2 + kp < kend2);
#pragma unroll
        for (int i = 0; i < 8; i++) ra[i] = (kok && vA[i]) ? pA[ofsA[i]] : 0u;
#pragma unroll
        for (int i = 0; i < 4; i++) rb4[i] = (kok && vB[i]) ? pB[ofsB[i]] : 0u;
    }

    for (int p0 = kbeg2; p0 < kend2; p0 += 16) {
#pragma unroll
        for (int i = 0; i < 8; i++) As[i * 16 + rg][kp] = ra[i];
#pragma unroll
        for (int i = 0; i < 4; i++) Bs[i * 16 + rg][kp] = rb4[i];
        __syncthreads();
        int pn = p0 + 16;
        if (pn < kend2) {
            pA += 16; pB += 16;
            bool kok = (pn + kp < kend2);
#pragma unroll
            for (int i = 0; i < 8; i++) ra[i] = (kok && vA[i]) ? pA[ofsA[i]] : 0u;
#pragma unroll
            for (int i = 0; i < 4; i++) rb4[i] = (kok && vB[i]) ? pB[ofsB[i]] : 0u;
        }
#pragma unroll
        for (int s = 0; s < 2; s++) {
            unsigned stepB = s * 32;
            unsigned a[2][4], b[4][2];
#pragma unroll
            for (int mt = 0; mt < 2; mt++) {
                unsigned ao = aOff + mt * (16 * 20 * 4) + stepB;
                ldsm_x4(a[mt][0], a[mt][1], a[mt][2], a[mt][3], sA + ao);
            }
#pragma unroll
            for (int p = 0; p < 2; p++) {
                unsigned bo = bOff + p * (16 * 20 * 4) + stepB;
                ldsm_x4(b[2*p][0], b[2*p][1], b[2*p+1][0], b[2*p+1][1], sB + bo);
            }
#pragma unroll
            for (int mt = 0; mt < 2; mt++)
#pragma unroll
                for (int nt = 0; nt < 4; nt++)
                    mma_f16(acc[mt][nt], a[mt], b[nt]);
        }
        __syncthreads();
    }
    int r_base = row0 + (warp_m << 5) + lq;
    int c_base = col0 + (warp_n << 5) + 2 * lr;
#pragma unroll
    for (int mt = 0; mt < 2; mt++) {
#pragma unroll
        for (int half = 0; half < 2; half++) {
            int r = r_base + mt * 16 + half * 8;
            if (r >= M) continue;
#pragma unroll
            for (int nt = 0; nt < 4; nt++) {
                int c = c_base + nt * 8;   // even
                float v0 = acc[mt][nt][half * 2];
                float v1 = acc[mt][nt][half * 2 + 1];
                if (PACKH1) {
                    long rb = (long)r * H1BW;
                    if (c < ALS1) {
                        CH[rb + (c >> 1)] = packHalf2(v0, v1);
                    } else {
                        if (c < H1W)     CH[rb + 390 + (c - ALS1)]     = __float_as_uint(v0);
                        if (c + 1 < H1W) CH[rb + 390 + (c + 1 - ALS1)] = __float_as_uint(v1);
                    }
                } else {
                    if (c < N)     C[(long)r * ldc + c] = v0;
                    if (c + 1 < N) C[(long)r * ldc + c + 1] = v1;
                }
            }
        }
    }
}

// ---------------- bf16-split GEMM (fc / conv layers) ----------------
template <bool BIAS, bool RELU, bool ATOMIC, bool PACKOUT>
__global__ __launch_bounds__(256, 2) void gemm_p(
        int M, int N, int K2,
        const unsigned* __restrict__ AH, const unsigned* __restrict__ AL, int lda2,
        const unsigned* __restrict__ BH, const unsigned* __restrict__ BL,
        float* __restrict__ C, int ldc,
        unsigned* __restrict__ CH, unsigned* __restrict__ CL, int ldc2,
        const float* __restrict__ bias, int kchunk2) {
    __shared__ unsigned AsH[128][20], AsL[128][20];
    __shared__ unsigned BsH[64][20],  BsL[64][20];
    int tid = threadIdx.x;
    int lane = tid & 31, warp = tid >> 5;
    int warp_m = warp & 3, warp_n = warp >> 2;
    int row0 = blockIdx.y * 128, col0 = blockIdx.x * 64;
    int kbeg2 = blockIdx.z * kchunk2;
    int kend2 = min(K2, kbeg2 + kchunk2);
    int lq = lane >> 2, lr = lane & 3;
    int kp = tid & 15;
    int rg = tid >> 4;

    unsigned sAH = (unsigned)__cvta_generic_to_shared(&AsH[0][0]);
    unsigned sAL = (unsigned)__cvta_generic_to_shared(&AsL[0][0]);
    unsigned sBH = (unsigned)__cvta_generic_to_shared(&BsH[0][0]);
    unsigned sBL = (unsigned)__cvta_generic_to_shared(&BsL[0][0]);
    unsigned aOff = (((warp_m << 5) + (lane & 15)) * 20 + ((lane >> 4) << 2)) * 4;
    unsigned bOff = (((warp_n << 5) + (((lane >> 4) & 1) << 3) + (lane & 7)) * 20
                     + (((lane >> 3) & 1) << 2)) * 4;

    float acc[2][4][4] = {};

    for (int p0 = kbeg2; p0 < kend2; p0 += 16) {
        bool kok = (p0 + kp < kend2);
#pragma unroll
        for (int i = 0; i < 8; i++) {
            int r = i * 16 + rg;
            bool ok = (row0 + r < M) && kok;
            long g = (long)(row0 + r) * lda2 + p0 + kp;
            AsH[r][kp] = ok ? AH[g] : 0u;
            AsL[r][kp] = ok ? AL[g] : 0u;
        }
#pragma unroll
        for (int i = 0; i < 4; i++) {
            int n = i * 16 + rg;
            bool ok = (col0 + n < N) && kok;
            long g = (long)(col0 + n) * K2 + p0 + kp;
            BsH[n][kp] = ok ? BH[g] : 0u;
            BsL[n][kp] = ok ? BL[g] : 0u;
        }
        __syncthreads();
#pragma unroll
        for (int s = 0; s < 2; s++) {
            unsigned stepB = s * 32;
            unsigned aH[2][4], aL[2][4], bH[4][2], bL[4][2];
#pragma unroll
            for (int mt = 0; mt < 2; mt++) {
                unsigned ao = aOff + mt * (16 * 20 * 4) + stepB;
                ldsm_x4(aH[mt][0], aH[mt][1], aH[mt][2], aH[mt][3], sAH + ao);
                ldsm_x4(aL[mt][0], aL[mt][1], aL[mt][2], aL[mt][3], sAL + ao);
            }
#pragma unroll
            for (int p = 0; p < 2; p++) {
                unsigned bo = bOff + p * (16 * 20 * 4) + stepB;
                ldsm_x4(bH[2*p][0], bH[2*p][1], bH[2*p+1][0], bH[2*p+1][1], sBH + bo);
                ldsm_x4(bL[2*p][0], bL[2*p][1], bL[2*p+1][0], bL[2*p+1][1], sBL + bo);
            }
#pragma unroll
            for (int mt = 0; mt < 2; mt++)
#pragma unroll
                for (int nt = 0; nt < 4; nt++) {
                    mma_bf16(acc[mt][nt], aH[mt], bH[nt]);
                    mma_bf16(acc[mt][nt], aH[mt], bL[nt]);
                    mma_bf16(acc[mt][nt], aL[mt], bH[nt]);
                }
        }
        __syncthreads();
    }
    int r_base = row0 + (warp_m << 5) + lq;
    int c_base = col0 + (warp_n << 5) + 2 * lr;
#pragma unroll
    for (int mt = 0; mt < 2; mt++) {
#pragma unroll
        for (int half = 0; half < 2; half++) {
            int r = r_base + mt * 16 + half * 8;
            if (r >= M) continue;
#pragma unroll
            for (int nt = 0; nt < 4; nt++) {
                int c = c_base + nt * 8;
                if (PACKOUT) {
                    float v0 = acc[mt][nt][half * 2];
                    float v1 = acc[mt][nt][half * 2 + 1];
                    if (BIAS) { v0 += bias[c]; v1 += bias[c + 1]; }
                    if (RELU) { v0 = fmaxf(v0, 0.f); v1 = fmaxf(v1, 0.f); }
                    if (c + 1 < N) {
                        unsigned H, L;
                        split2pack(v0, v1, H, L);
                        CH[(long)r * ldc2 + (c >> 1)] = H;
                        CL[(long)r * ldc2 + (c >> 1)] = L;
                    }
                } else {
#pragma unroll
                    for (int j = 0; j < 2; j++) {
                        int cc = c + j;
                        if (cc >= N) continue;
                        float v = acc[mt][nt][half * 2 + j];
                        if (ATOMIC) {
                            atomicAdd(&C[(long)r * ldc + cc], v);
                        } else {
                            if (BIAS) v += bias[cc];
                            if (RELU) v = fmaxf(v, 0.f);
                            C[(long)r * ldc + cc] = v;
                        }
                    }
                }
            }
        }
    }
}

__global__ void bias_init_k(float* C, int ldc, int M, int N, const float* __restrict__ bias) {
    int idx = blockIdx.x * blockDim.x + threadIdx.x;
    if (idx < M * N) { int r = idx / N, c = idx % N; C[(long)r * ldc + c] = bias[c]; }
}

// ---------------- GAT layer 1 aggregation: WARP PER NODE (round-12 u32 version) ----------------
__global__ __launch_bounds__(256) void agg1_k(
        const unsigned* __restrict__ h1b, const int* __restrict__ off,
        const int* __restrict__ srcs, const float* __restrict__ b1,
        const float* __restrict__ ws, const float* __restrict__ wd,
        unsigned* __restrict__ outF,
        float* __restrict__ als2, float* __restrict__ ald2) {
    int gw = (blockIdx.x * blockDim.x + threadIdx.x) >> 5;
    int lane = threadIdx.x & 31;
    if (gw >= N_NODES) return;
    int i = gw;
    int base = off[i];
    int deg = off[i + 1] - base;
    float aldi = (lane < NH1) ? __uint_as_float(h1b[(long)i * H1BW + 400 + lane]) : 0.f;
    float denom = 0.f;
    float ax[13], ay[13];
#pragma unroll
    for (int j = 0; j < 13; j++) { ax[j] = 0.f; ay[j] = 0.f; }
    int hp[13];
#pragma unroll
    for (int j = 0; j < 13; j++) {
        int p = j * 32 + lane;
        hp[j] = (p < K2_D1 ? p : K2_D1 - 1) / 39;
    }
    for (int e = 0; e < deg; e++) {
        int src = srcs[base + e];
        const unsigned* hr = h1b + (long)src * H1BW;
        float we = 0.f;
        if (lane < NH1) {
            float l = __uint_as_float(hr[390 + lane]) + aldi;
            l = l > 0.f ? l : 0.2f * l;
            we = expf(l);
            denom += we;
        }
#pragma unroll
        for (int j = 0; j < 13; j++) {
            int p = j * 32 + lane;
            unsigned u = (p < K2_D1) ? hr[p] : 0u;
            float wj = __shfl_sync(0xffffffffu, we, hp[j]);
            float2 f = __half22float2(*reinterpret_cast<const __half2*>(&u));
            ax[j] += wj * f.x;
            ay[j] += wj * f.y;
        }
    }
    float sinv = 1.f / (denom + 1e-16f);  // valid in lanes 0..9
    float cs = 0.f, cd = 0.f;
    long ob = (long)i * K2_D1;
#pragma unroll
    for (int j = 0; j < 13; j++) {
        int p = j * 32 + lane;
        float sv = __shfl_sync(0xffffffffu, sinv, hp[j]);
        if (p < K2_D1) {
            float v0 = ax[j] * sv + b1[2 * p];
            v0 = v0 > 0.f ? v0 : expf(v0) - 1.f;
            float v1 = ay[j] * sv + b1[2 * p + 1];
            v1 = v1 > 0.f ? v1 : expf(v1) - 1.f;
            cs += v0 * ws[2 * p] + v1 * ws[2 * p + 1];
            cd += v0 * wd[2 * p] + v1 * wd[2 * p + 1];
            outF[ob + p] = packHalf2(v0, v1);
        }
    }
#pragma unroll
    for (int o = 16; o; o >>= 1) {
        cs += __shfl_down_sync(0xffffffffu, cs, o);
        cd += __shfl_down_sync(0xffffffffu, cd, o);
    }
    if (lane == 0) { als2[i] = cs; ald2[i] = cd; }
}

// ---------------- GAT layer 2 aggregation: WARP PER NODE (round-12 version) ----------------
__global__ __launch_bounds__(256) void agg2_k(
        const float* __restrict__ h2, const float* __restrict__ als,
        const float* __restrict__ ald, const int* __restrict__ off,
        const int* __restrict__ srcs, const float* __restrict__ b2,
        float* __restrict__ out) {
    int gw = (blockIdx.x * blockDim.x + threadIdx.x) >> 5;
    int lane = threadIdx.x & 31;
    if (gw >= N_NODES) return;
    int i = gw;
    int base = off[i];
    int deg = off[i + 1] - base;
    float aldi = ald[i];
    float denom = 0.f;
    float a0 = 0.f, a1 = 0.f, a2 = 0.f, a3 = 0.f;
    for (int e = 0; e < deg; e++) {
        int src = srcs[base + e];
        float l = als[src] + aldi;
        l = l > 0.f ? l : 0.2f * l;
        float w = expf(l);
        denom += w;
        const float* hr = h2 + (long)src * C2;
        a0 += w * hr[lane];
        a1 += w * hr[lane + 32];
        a2 += w * hr[lane + 64];
        a3 += w * hr[lane + 96];
    }
    float sinv = 1.f / (denom + 1e-16f);
    long ob = (long)i * C2;
    out[ob + lane]      = fmaxf(a0 * sinv + b2[lane], 0.f);
    out[ob + lane + 32] = fmaxf(a1 * sinv + b2[lane + 32], 0.f);
    out[ob + lane + 64] = fmaxf(a2 * sinv + b2[lane + 64], 0.f);
    out[ob + lane + 96] = fmaxf(a3 * sinv + b2[lane + 96], 0.f);
}

// ---------------- starts ----------------
__global__ void starts_k(const int* __restrict__ batch, int* starts) {
    int i = blockIdx.x * blockDim.x + threadIdx.x;
    if (i >= N_NODES) return;
    if (i == 0) starts[0] = 0;
    else if (batch[i] != batch[i - 1]) starts[batch[i]] = i;
    if (i == N_NODES - 1) starts[BATCH] = N_NODES;
}

// ---------------- fused pool + fc_g1 + pack ----------------
__global__ void poolfc_k(const float* __restrict__ o2, const int* __restrict__ starts,
                         const float* __restrict__ fgw, const float* __restrict__ fgb,
                         unsigned* __restrict__ XH, unsigned* __restrict__ XL) {
    int b = blockIdx.x, c = threadIdx.x;  // 128 threads
    __shared__ float pool[C2];
    int s = starts[b], e = starts[b + 1];
    float m = -1e30f;
    for (int r = s; r < e; r++) m = fmaxf(m, o2[(long)r * C2 + c]);
    pool[c] = m;
    __syncthreads();
    float acc = fgb[c];
#pragma unroll 8
    for (int k = 0; k < C2; k++) acc += pool[k] * fgw[k * C2 + c];
    acc = fmaxf(acc, 0.f);
    float p = __shfl_xor_sync(0xffffffffu, acc, 1);
    if (!(c & 1)) {
        unsigned H, L; split2pack(acc, p, H, L);
        XH[b * K2_F1 + (c >> 1)] = H;
        XL[b * K2_F1 + (c >> 1)] = L;
    }
}

// ---------------- conv branch ----------------
__global__ void scatterA_k(const int* __restrict__ target, const float* __restrict__ cw,
                           unsigned* __restrict__ AH, unsigned* __restrict__ AL) {
    int b = blockIdx.x, tid = threadIdx.x;
    __shared__ float Ash[NF * VOCAB * KW];
    for (int i = tid; i < NF * VOCAB * KW; i += 256) Ash[i] = 0.f;
    __syncthreads();
    int o = tid >> 3, k = tid & 7;
    const float* wrow = cw + o * (SEQ * KW) + k;
    float* arow = Ash + o * (VOCAB * KW) + k;
    for (int s = 0; s < SEQ; s++) {
        int v = target[b * SEQ + s];
        arow[v * KW] += wrow[s * KW];
    }
    __syncthreads();
    for (int i = tid; i < NF * K2_CV; i += 256) {
        int o2_ = i / K2_CV, kp = i - o2_ * K2_CV;
        unsigned H, L;
        split2pack(Ash[o2_ * (VOCAB * KW) + 2 * kp], Ash[o2_ * (VOCAB * KW) + 2 * kp + 1], H, L);
        long g = ((long)b * NF + o2_) * K2_CV + kp;
        AH[g] = H; AL[g] = L;
    }
}
__global__ void conv_epi_k(const float* __restrict__ c, const float* __restrict__ cb,
                           unsigned* __restrict__ outH, unsigned* __restrict__ outL) {
    int idx = blockIdx.x * blockDim.x + threadIdx.x;
    if (idx >= BATCH * NF * LOUT) return;
    int o = (idx / LOUT) & (NF - 1);
    float v = fmaxf(c[idx] + cb[o], 0.f);
    float p = __shfl_xor_sync(0xffffffffu, v, 1);
    if (!(idx & 1)) {
        unsigned H, L; split2pack(v, p, H, L);
        outH[idx >> 1] = H; outL[idx >> 1] = L;
    }
}
__global__ void xtpack_k(const float* __restrict__ xt, unsigned* __restrict__ XH, unsigned* __restrict__ XL) {
    int idx = blockIdx.x * blockDim.x + threadIdx.x;
    if (idx >= BATCH * 64) return;
    int r = idx >> 6, p = idx & 63;
    unsigned H, L;
    split2pack(xt[r * C2 + 2 * p], xt[r * C2 + 2 * p + 1], H, L);
    XH[r * K2_F1 + 64 + p] = H; XL[r * K2_F1 + 64 + p] = L;
}

// ---------------- final ----------------
__global__ void final_k(const float* __restrict__ x, const float* __restrict__ w,
                        const float* __restrict__ b, float* __restrict__ y) {
    int gw = (blockIdx.x * blockDim.x + threadIdx.x) >> 5;
    int lane = threadIdx.x & 31;
    if (gw >= BATCH) return;
    float s = 0.f;
#pragma unroll
    for (int j = lane; j < 256; j += 32) s += x[gw * 256 + j] * w[j];
#pragma unroll
    for (int o = 16; o; o >>= 1) s += __shfl_down_sync(0xffffffffu, s, o);
    if (lane == 0) y[gw] = s + b[0];
}

// ---------------- host ----------------
extern "C" void kernel_launch(void* const* d_in, const int* in_sizes, int n_in,
                              void* d_out, int out_size) {
    const float* x       = (const float*)d_in[0];
    const int*   ei      = (const int*)d_in[1];
    const int*   batch   = (const int*)d_in[2];
    const int*   target  = (const int*)d_in[3];
    const float* W1      = (const float*)d_in[4];
    const float* a_src1  = (const float*)d_in[5];
    const float* a_dst1  = (const float*)d_in[6];
    const float* b1      = (const float*)d_in[7];
    const float* W2      = (const float*)d_in[8];
    const float* a_src2  = (const float*)d_in[9];
    const float* a_dst2  = (const float*)d_in[10];
    const float* b2      = (const float*)d_in[11];
    const float* fc_g1_w = (const float*)d_in[12];
    const float* fc_g1_b = (const float*)d_in[13];
    const float* emb     = (const float*)d_in[14];
    const float* conv_w  = (const float*)d_in[15];
    const float* conv_b  = (const float*)d_in[16];
    const float* fc_xt_w = (const float*)d_in[17];
    const float* fc_xt_b = (const float*)d_in[18];
    const float* fc1_w   = (const float*)d_in[19];
    const float* fc1_b   = (const float*)d_in[20];
    const float* fc2_w   = (const float*)d_in[21];
    const float* fc2_b   = (const float*)d_in[22];
    const float* out_w   = (const float*)d_in[23];
    const float* out_b   = (const float*)d_in[24];
    float* y = (float*)d_out;
    int E = in_sizes[1] / 2;

    float *h2p, *o2p, *convp, *xtp, *f2p, *wsp, *wdp, *als2p, *ald2p;
    unsigned *h1bp, *xFp, *w1Fp, *h1eFp, *w2Fp;
    unsigned *AHp, *ALp, *EkHp, *EkLp;
    unsigned *cvHp, *cvLp, *fxtHp, *fxtLp, *xcHp, *xcLp, *f1wHp, *f1wLp;
    unsigned *f1Hp, *f1Lp, *f2wHp, *f2wLp;
    int *degp, *offp, *curp, *srcsp, *startsp;
    cudaGetSymbolAddress((void**)&h1bp, g_h1b);
    cudaGetSymbolAddress((void**)&h2p, g_h2);
    cudaGetSymbolAddress((void**)&o2p, g_o2);
    cudaGetSymbolAddress((void**)&convp, g_conv);
    cudaGetSymbolAddress((void**)&xtp, g_xt);
    cudaGetSymbolAddress((void**)&f2p, g_f2);
    cudaGetSymbolAddress((void**)&wsp, g_ws);   cudaGetSymbolAddress((void**)&wdp, g_wd);
    cudaGetSymbolAddress((void**)&als2p, g_als2); cudaGetSymbolAddress((void**)&ald2p, g_ald2);
    cudaGetSymbolAddress((void**)&xFp, g_xF);
    cudaGetSymbolAddress((void**)&w1Fp, g_w1F);
    cudaGetSymbolAddress((void**)&h1eFp, g_h1eF);
    cudaGetSymbolAddress((void**)&w2Fp, g_w2F);
    cudaGetSymbolAddress((void**)&AHp, g_AH);   cudaGetSymbolAddress((void**)&ALp, g_AL);
    cudaGetSymbolAddress((void**)&EkHp, g_EkH); cudaGetSymbolAddress((void**)&EkLp, g_EkL);
    cudaGetSymbolAddress((void**)&cvHp, g_cvH); cudaGetSymbolAddress((void**)&cvLp, g_cvL);
    cudaGetSymbolAddress((void**)&fxtHp, g_fxtH); cudaGetSymbolAddress((void**)&fxtLp, g_fxtL);
    cudaGetSymbolAddress((void**)&xcHp, g_xcH); cudaGetSymbolAddress((void**)&xcLp, g_xcL);
    cudaGetSymbolAddress((void**)&f1wHp, g_f1wH); cudaGetSymbolAddress((void**)&f1wLp, g_f1wL);
    cudaGetSymbolAddress((void**)&f1Hp, g_f1H); cudaGetSymbolAddress((void**)&f1Lp, g_f1L);
    cudaGetSymbolAddress((void**)&f2wHp, g_f2wH); cudaGetSymbolAddress((void**)&f2wLp, g_f2wL);
    cudaGetSymbolAddress((void**)&degp, g_deg);
    cudaGetSymbolAddress((void**)&offp, g_off);
    cudaGetSymbolAddress((void**)&curp, g_cur);
    cudaGetSymbolAddress((void**)&srcsp, g_srcs);
    cudaGetSymbolAddress((void**)&startsp, g_starts);

    static cudaStream_t s1 = nullptr, s2 = nullptr;
    static cudaEvent_t evRoot = nullptr, evPrep = nullptr, evCSR = nullptr, evConv = nullptr;
    if (!s1) {
        cudaStreamCreateWithFlags(&s1, cudaStreamNonBlocking);
        cudaStreamCreateWithFlags(&s2, cudaStreamNonBlocking);
        cudaEventCreateWithFlags(&evRoot, cudaEventDisableTiming);
        cudaEventCreateWithFlags(&evPrep, cudaEventDisableTiming);
        cudaEventCreateWithFlags(&evCSR, cudaEventDisableTiming);
        cudaEventCreateWithFlags(&evConv, cudaEventDisableTiming);
    }

    // fork
    cudaEventRecord(evRoot, 0);
    cudaStreamWaitEvent(s1, evRoot, 0);
    cudaStreamWaitEvent(s2, evRoot, 0);

    // #1 prep (s0); CSR on s1; #4 on s0 = GEMM1 -> ncu window
    prep_k<<<PB_EK, 256>>>(x, W1, a_src1, a_dst1, W2, a_src2, a_dst2,
                           fc_xt_w, fc1_w, fc2_w, emb,
                           xFp, w1Fp, w2Fp, wsp, wdp,
                           fxtHp, fxtLp, f1wHp, f1wLp,
                           f2wHp, f2wLp, EkHp, EkLp);
    cudaEventRecord(evPrep, 0);
    deg_init_k<<<(N_NODES + 255) / 256, 256, 0, s1>>>(degp);
    hist_k<<<(E + 255) / 256, 256, 0, s1>>>(ei, degp, E);
    {   // GEMM1 (f16, pipelined, hoisted): [50000, 800] -> hybrid packed h1b
        dim3 g((H1W + 63) / 64, (N_NODES + 127) / 128);
        gemm_h<true><<<g, 256>>>(N_NODES, H1W, K2_X,
            xFp, K2_X, w1Fp, nullptr, 0, h1bp, K2_X);
    }
    scan_k<<<1, 1024, 0, s1>>>(degp, offp, N_NODES);
    selfloop_k<<<(N_NODES + 255) / 256, 256, 0, s1>>>(offp, curp, srcsp);
    fill_k<<<(E + 255) / 256, 256, 0, s1>>>(ei, curp, srcsp, E);
    starts_k<<<(N_NODES + 255) / 256, 256, 0, s1>>>(batch, startsp);
    cudaEventRecord(evCSR, s1);

    // s2: conv branch
    scatterA_k<<<BATCH, 256, 0, s2>>>(target, conv_w, AHp, ALp);
    cudaStreamWaitEvent(s2, evPrep, 0);
    {
        dim3 g((LOUT + 63) / 64, (BATCH * NF + 127) / 128);
        gemm_p<false, false, false, false><<<g, 256, 0, s2>>>(BATCH * NF, LOUT, K2_CV,
            AHp, ALp, K2_CV, EkHp, EkLp, convp, LOUT, nullptr, nullptr, 0, nullptr, K2_CV);
    }
    conv_epi_k<<<(BATCH * NF * LOUT + 255) / 256, 256, 0, s2>>>(convp, conv_b, cvHp, cvLp);
    bias_init_k<<<(BATCH * C2 + 255) / 256, 256, 0, s2>>>(xtp, C2, BATCH, C2, fc_xt_b);
    {
        dim3 g(2, 4, 8);
        gemm_p<false, false, true, false><<<g, 256, 0, s2>>>(BATCH, C2, K2_XT,
            cvHp, cvLp, K2_XT, fxtHp, fxtLp, xtp, C2, nullptr, nullptr, 0, nullptr, 242);
    }
    xtpack_k<<<(BATCH * 64 + 255) / 256, 256, 0, s2>>>(xtp, xcHp, xcLp);
    cudaEventRecord(evConv, s2);

    // s0 main chain
    cudaStreamWaitEvent(0, evCSR, 0);
    agg1_k<<<(N_NODES * 32 + 255) / 256, 256>>>(h1bp, offp, srcsp, b1, wsp, wdp, h1eFp, als2p, ald2p);
    {   // GEMM2 (f16, pipelined, hoisted): [50000, 128]
        dim3 g(2, (N_NODES + 127) / 128);
        gemm_h<false><<<g, 256>>>(N_NODES, C2, K2_D1,
            h1eFp, K2_D1, w2Fp, h2p, C2, nullptr, K2_D1);
    }
    agg2_k<<<(N_NODES * 32 + 255) / 256, 256>>>(h2p, als2p, ald2p, offp, srcsp, b2, o2p);
    poolfc_k<<<BATCH, C2>>>(o2p, startsp, fc_g1_w, fc_g1_b, xcHp, xcLp);
    cudaStreamWaitEvent(0, evConv, 0);
    {   // fc1
        dim3 g(16, 4);
        gemm_p<true, true, false, true><<<g, 256>>>(BATCH, 1024, K2_F1,
            xcHp, xcLp, K2_F1, f1wHp, f1wLp, nullptr, 0, f1Hp, f1Lp, K2_F2, fc1_b, K2_F1);
    }
    {   // fc2
        dim3 g(4, 4);
        gemm_p<true, true, false, false><<<g, 256>>>(BATCH, 256, K2_F2,
            f1Hp, f1Lp, K2_F2, f2wHp, f2wLp, f2p, 256, nullptr, nullptr, 0, fc2_b, K2_F2);
    }
    final_k<<<64, 256>>>(f2p, out_w, out_b, y);
}